// round 14
// baseline (speedup 1.0000x reference)
#include <cuda_runtime.h>
#include <cuda_bf16.h>

#define NB    8
#define NV    2048
#define NF    512
#define VOX   96

#define STEPF (2.0f / 96.0f)
#define PZ0F  (-95.0f / 96.0f)

// Interval record, 4 float4 per facet, rows r=0..2,s:
//  row = (Ex, Ey, Ec, w):  lo_r = Ex*px + Ey*py + Ec ;  hi_r = lo_r + w (w>=0)
__device__ float4 g_int[NB * NF * 4];
// Exact record (bit-identical R2 form), 4 float4 per facet:
//  e0 = B00 B01 B02 |det|   e1 = B10 B11 B12 v3x
//  e2 = B20 B21 B22 v3y     e3 = v3z pad pad pad
__device__ float4 g_ex[NB * NF * 4];
// Packed bbox: {ixLo, ixHi, iyLo|(iyHi<<8), dfexp}
__device__ int4 g_bb[NB * NF];

// ---------------------------------------------------------------------------
// Prep: one thread per facet.
// ---------------------------------------------------------------------------
__global__ void prep_kernel(
    const float* __restrict__ vertices,   // [NB, NV, 3] f32
    const int*   __restrict__ facets)     // [NB, NF, 4] i32
{
    const int id = blockIdx.x * 256 + threadIdx.x;   // < NB*NF
    const int b = id >> 9;

    const float* Vb = vertices + (size_t)b * NV * 3;
    const int* Fp = facets + (size_t)id * 4;
    const int i0 = Fp[0] & (NV - 1);
    const int i1 = Fp[1] & (NV - 1);
    const int i2 = Fp[2] & (NV - 1);
    const int i3 = Fp[3] & (NV - 1);

    const float v0x = Vb[i0*3+0], v0y = Vb[i0*3+1], v0z = Vb[i0*3+2];
    const float v1x = Vb[i1*3+0], v1y = Vb[i1*3+1], v1z = Vb[i1*3+2];
    const float v2x = Vb[i2*3+0], v2y = Vb[i2*3+1], v2z = Vb[i2*3+2];
    const float v3x = Vb[i3*3+0], v3y = Vb[i3*3+1], v3z = Vb[i3*3+2];

    const float a  = v0x - v3x, bb = v1x - v3x, c  = v2x - v3x;
    const float d  = v0y - v3y, e  = v1y - v3y, ff = v2y - v3y;
    const float g  = v0z - v3z, h  = v1z - v3z, ii = v2z - v3z;

    const float A00 = e*ii - ff*h, A01 = c*h  - bb*ii, A02 = bb*ff - c*e;
    const float A10 = ff*g - d*ii, A11 = a*ii - c*g,   A12 = c*d  - a*ff;
    const float A20 = d*h  - e*g,  A21 = bb*g - a*h,   A22 = a*e  - bb*d;

    const float det = a*A00 + bb*A10 + c*A20;
    const float sd  = (det < 0.0f) ? -1.0f : 1.0f;
    float D = det * sd;
    if (det == 0.0f) D = -1.0f;

    const float B[3][3] = { {A00*sd, A01*sd, A02*sd},
                            {A10*sd, A11*sd, A12*sd},
                            {A20*sd, A21*sd, A22*sd} };

    g_ex[id*4+0] = make_float4(B[0][0], B[0][1], B[0][2], D);
    g_ex[id*4+1] = make_float4(B[1][0], B[1][1], B[1][2], v3x);
    g_ex[id*4+2] = make_float4(B[2][0], B[2][1], B[2][2], v3y);
    g_ex[id*4+3] = make_float4(v3z, 0.0f, 0.0f, 0.0f);

    float R0[4], R1[4], Kc[4], Bz[4];
    #pragma unroll
    for (int r = 0; r < 3; r++) {
        R0[r] = B[r][0]; R1[r] = B[r][1];
        float bz = B[r][2];
        if (fabsf(bz) < 1e-30f) bz = 1e-30f;
        Bz[r] = bz;
        Kc[r] = bz * (PZ0F - v3z) - B[r][0]*v3x - B[r][1]*v3y;
    }
    R0[3] = R0[0] + R0[1] + R0[2];
    R1[3] = R1[0] + R1[1] + R1[2];
    {
        float bz = Bz[0] + Bz[1] + Bz[2];
        if (fabsf(bz) < 1e-30f) bz = 1e-30f;
        Bz[3] = bz;
        Kc[3] = Kc[0] + Kc[1] + Kc[2];
    }

    float M = 0.0f;
    #pragma unroll
    for (int r = 0; r < 4; r++) {
        const float G   = Bz[r] * STEPF;
        const float nG  = -1.0f / G;
        const float DoG = D / G;
        const float Ex  = R0[r] * nG;
        const float Ey  = R1[r] * nG;
        const float Ec  = Kc[r] * nG + fminf(DoG, 0.0f);
        const float w   = fabsf(DoG);
        g_int[id*4+r] = make_float4(Ex, Ey, Ec, w);
        M = fmaxf(M, fabsf(Ex) + fabsf(Ey) + fabsf(Ec) + w);
    }
    const float delta = fmaf(M, 4e-6f, 2e-6f);   // conservative endpoint bound

    // round delta UP to a power of two -> 8-bit exponent (safe: only widens band)
    int dfexp;
    if (delta < 0.4f) {
        const unsigned dbits = __float_as_uint(delta);
        dfexp = (int)((dbits >> 23) & 0xFFu) + ((dbits & 0x7FFFFFu) ? 1 : 0);
    } else {
        dfexp = 0xFF;   // pathological facet -> all-exact path
    }

    // voxel bbox with safety pad
    const float pad = 1e-5f;
    const float xmn = fminf(fminf(v0x, v1x), fminf(v2x, v3x)) - pad;
    const float xmx = fmaxf(fmaxf(v0x, v1x), fmaxf(v2x, v3x)) + pad;
    const float ymn = fminf(fminf(v0y, v1y), fminf(v2y, v3y)) - pad;
    const float ymx = fmaxf(fmaxf(v0y, v1y), fmaxf(v2y, v3y)) + pad;

    int4 bbv;
    bbv.x = max(0,  (int)ceilf (48.0f * xmn + 47.5f));
    bbv.y = min(95, (int)floorf(48.0f * xmx + 47.5f));
    const int iyLo = max(0,  (int)ceilf (48.0f * ymn + 47.5f));
    const int iyHi = min(95, (int)floorf(48.0f * ymx + 47.5f));
    bbv.z = iyLo | (iyHi << 8);
    bbv.w = dfexp;
    if (D < 0.0f || iyLo > iyHi) { bbv.x = 1; bbv.y = 0; }   // empty
    g_bb[id] = bbv;
}

// ---------------------------------------------------------------------------
// Voxelize: block = (x-plane, batch), 384 threads = 12 warps, 4 blocks/SM.
// Warp = (y-tile t = warp>>2, facet-quarter q = warp&3); lane owns column
// iy = t*32+lane, mask in 3 registers. Tile-list entries are single ints
// packing pos|iyLo|iyHi|dfexp, so the common path does ONE list LDS + the
// coefficient LDS. Range masks via smem prefix LUT. Exact band rare, from L2.
// ---------------------------------------------------------------------------
#define LUTP 104   // padded stride per word row

__global__ void __launch_bounds__(384, 4) vox_kernel(float* __restrict__ out)
{
    __shared__ float4   sfac[NF * 3];     // 24576 B (Ey,Ec',w rows packed)
    __shared__ int      sfid[NF];         //  2048 B  facet id per pos (band only)
    __shared__ int      tlist[3][NF];     //  6144 B  packed entries
    __shared__ unsigned sGE[3 * LUTP];    //  1248 B: word w of bits >= k
    __shared__ unsigned sLT[3 * LUTP];    //  1248 B: word w of bits <  k
    __shared__ unsigned sacc[VOX * 3];    //  1152 B
    __shared__ int      tcnt[3];
    __shared__ int      pcnt;

    const int tid = threadIdx.x;
    // center-out plane remap: heavy central planes get scheduled first
    const int i  = blockIdx.x;
    const int plane = (i & 1) ? (47 - (i >> 1)) : (48 + (i >> 1));
    const int b     = blockIdx.y;

    if (tid < 3) tcnt[tid] = 0;
    if (tid == 3) pcnt = 0;
    for (int s = tid; s < VOX * 3; s += 384) sacc[s] = 0u;
    // build prefix-mask LUT: 3 words x 97 entries
    for (int s = tid; s < 3 * 97; s += 384) {
        const int w = s / 97;
        const int k = s - w * 97;
        const int sh = k - 32 * w;
        unsigned ge, lt;
        if (sh <= 0)       { ge = 0xFFFFFFFFu; lt = 0u; }
        else if (sh >= 32) { ge = 0u;          lt = 0xFFFFFFFFu; }
        else               { ge = 0xFFFFFFFFu << sh; lt = 0xFFFFFFFFu >> (32 - sh); }
        sGE[w * LUTP + k] = ge;
        sLT[w * LUTP + k] = lt;
    }
    __syncthreads();

    const float px = (float)(2 * plane + 1 - VOX) / 96.0f;

    // fused compaction + staging
    for (int j = tid; j < NF; j += 384) {
        const int4 bb = g_bb[b * NF + j];
        if (plane < bb.x || plane > bb.y) continue;
        const int pos = atomicAdd(&pcnt, 1);
        const int iyLo = bb.z & 0xFF, iyHi = (bb.z >> 8) & 0xFF;
        sfid[pos] = j;
        const int entry = pos | (iyLo << 9) | (iyHi << 16) | (bb.w << 23);
        for (int t = iyLo >> 5; t <= iyHi >> 5; t++) {
            const int tp = atomicAdd(&tcnt[t], 1);
            tlist[t][tp] = entry;
        }
        const float4* gi = g_int + ((size_t)b * NF + j) * 4;
        const float4 r0 = gi[0], r1 = gi[1], r2 = gi[2], r3 = gi[3];
        const float Ec0 = fmaf(r0.x, px, r0.z);
        const float Ec1 = fmaf(r1.x, px, r1.z);
        const float Ec2 = fmaf(r2.x, px, r2.z);
        const float Ec3 = fmaf(r3.x, px, r3.z);
        sfac[pos*3+0] = make_float4(r0.y, Ec0, r0.w, r1.y);
        sfac[pos*3+1] = make_float4(Ec1, r1.w, r2.y, Ec2);
        sfac[pos*3+2] = make_float4(r2.w, r3.y, Ec3, r3.w);
    }
    __syncthreads();

    const int warp = tid >> 5;
    const int lane = tid & 31;
    const int t = warp >> 2;        // y-tile 0..2
    const int q = warp & 3;         // facet quarter 0..3

    const int   iy = t * 32 + lane;
    const float py = (float)(2 * iy + 1 - VOX) / 96.0f;

    unsigned m0 = 0u, m1 = 0u, m2 = 0u;
    const int myn = tcnt[t];

    for (int ii = q; ii < myn; ii += 4) {
        const int e = tlist[t][ii];
        const int iyLo = (e >> 9)  & 0x7F;
        const int iyHi = (e >> 16) & 0x7F;
        if (iy < iyLo || iy > iyHi) continue;
        const int pos = e & 0x1FF;

        const float4 a0 = sfac[pos*3+0];
        const float4 a1 = sfac[pos*3+1];
        const float4 a2 = sfac[pos*3+2];

        const float lo0 = fmaf(a0.x, py, a0.y);
        const float lo1 = fmaf(a0.w, py, a1.x);
        const float lo2 = fmaf(a1.z, py, a1.w);
        const float lo3 = fmaf(a2.y, py, a2.z);

        const float tlo = fmaxf(fmaxf(lo0, lo1), fmaxf(lo2, lo3));
        const float thi = fminf(fminf(lo0 + a0.z, lo1 + a1.y),
                                fminf(lo2 + a2.x, lo3 + a2.w));

        // delta = power-of-two from packed exponent bits (one AND)
        const float df = __uint_as_float((unsigned)e & 0xFF800000u);
        const bool allex = !(df <= 0.4f);   // dfexp==0xFF (inf) or NaN

        int kLo, kHi, cLo, cHi;
        if (allex) {
            kLo = 0; kHi = 95; cLo = 96; cHi = -1;
        } else {
            kLo = max(0,  __float2int_ru(tlo - df));
            kHi = min(95, __float2int_rd(thi + df));
            if (kLo > kHi) continue;
            cLo = kLo + (((float)kLo < tlo + df) ? 1 : 0);
            cHi = kHi - (((float)kHi > thi - df) ? 1 : 0);
        }

        // clear-region mask via prefix LUT (empty case falls out as 0)
        {
            const int aI = cLo;          // 0..96
            const int bI = cHi + 1;      // 0..96
            m0 |= sGE[aI]            & sLT[bI];
            m1 |= sGE[LUTP + aI]     & sLT[LUTP + bI];
            m2 |= sGE[2 * LUTP + aI] & sLT[2 * LUTP + bI];
        }

        if (kLo < cLo || cHi < kHi) {
            // rare band: exact re-test (reference-identical form), L2-resident
            const int fid = sfid[pos];
            const float4* ep = g_ex + ((size_t)b * NF + fid) * 4;
            const float4 e0 = __ldg(ep + 0);
            const float4 e1 = __ldg(ep + 1);
            const float4 e2 = __ldg(ep + 2);
            const float4 e3 = __ldg(ep + 3);
            const float dx = px - e1.w;
            const float dy = py - e2.w;
            for (int k = kLo; k <= kHi; k++) {
                if (k >= cLo && k <= cHi) { k = cHi; continue; }
                const float pz = (float)(2 * k + 1 - VOX) / 96.0f;
                const float dz = pz - e3.x;
                const float n0 = fmaf(e0.x, dx, fmaf(e0.y, dy, e0.z * dz));
                const float n1 = fmaf(e1.x, dx, fmaf(e1.y, dy, e1.z * dz));
                const float n2 = fmaf(e2.x, dx, fmaf(e2.y, dy, e2.z * dz));
                const float s  = n0 + n1 + n2;
                const float lo = fminf(fminf(n0, n1), fminf(n2, s));
                const float hi = fmaxf(fmaxf(n0, n1), fmaxf(n2, s));
                if (lo >= 0.0f && hi <= e0.w) {
                    if (k < 32)      m0 |= 1u << k;
                    else if (k < 64) m1 |= 1u << (k - 32);
                    else             m2 |= 1u << (k - 64);
                }
            }
        }
    }

    // merge the 4 quarter-warps per column (block-local)
    if (m0) atomicOr(&sacc[iy * 3 + 0], m0);
    if (m1) atomicOr(&sacc[iy * 3 + 1], m1);
    if (m2) atomicOr(&sacc[iy * 3 + 2], m2);
    __syncthreads();

    // coalesced expand: 96 columns * 24 float4 each
    float4* o4 = reinterpret_cast<float4*>(
        out + ((size_t)(b * VOX + plane) * VOX) * VOX);
    for (int idx = tid; idx < VOX * 24; idx += 384) {
        const int c = idx / 24;
        const int j = idx - c * 24;
        const unsigned word = sacc[c * 3 + (j >> 3)];
        const unsigned nib = (word >> ((j & 7) * 4)) & 0xFu;
        float4 v;
        v.x = (nib & 1u) ? 1.0f : 0.0f;
        v.y = (nib & 2u) ? 1.0f : 0.0f;
        v.z = (nib & 4u) ? 1.0f : 0.0f;
        v.w = (nib & 8u) ? 1.0f : 0.0f;
        o4[c * 24 + j] = v;
    }
}

extern "C" void kernel_launch(void* const* d_in, const int* in_sizes, int n_in,
                              void* d_out, int out_size)
{
    const float* vertices = (const float*)d_in[0];   // [8, 2048, 3] f32
    const int*   facets   = (const int*)d_in[1];     // [8, 512, 4]  i32
    float* out = (float*)d_out;                      // [8, 96, 96, 96] f32

    prep_kernel<<<16, 256>>>(vertices, facets);
    dim3 grid(VOX, NB);
    vox_kernel<<<grid, 384>>>(out);
}